// round 1
// baseline (speedup 1.0000x reference)
#include <cuda_runtime.h>

#define D_MODEL 1024
#define NHEADS  16
#define DK      64
#define BATCH   4
#define SEQ     2048
#define MROWS   (BATCH*SEQ)   // 8192

// Scratch buffers (allocation-free rule: __device__ globals)
__device__ float g_q[MROWS * D_MODEL];
__device__ float g_k[MROWS * D_MODEL];
__device__ float g_v[MROWS * D_MODEL];
__device__ float g_att[MROWS * D_MODEL];

// ---------------------------------------------------------------------------
// GEMM: C[m,n] = sum_k A[m,k] * W[n,k] + bias[n]   (y = x @ W^T + b)
// A: M x K row-major, W: N x K row-major. M=8192, N=K=1024 here.
// 128x128 block tile, BK=8, 256 threads, 8x8 per-thread micro-tile.
// ---------------------------------------------------------------------------
#define GBM 128
#define GBN 128
#define GBK 8

__global__ __launch_bounds__(256, 2)
void gemm_nt_bias(const float* __restrict__ A, const float* __restrict__ W,
                  const float* __restrict__ bias, float* __restrict__ C,
                  int M, int N, int K)
{
    __shared__ float As[GBK][GBM];
    __shared__ float Bs[GBK][GBN];

    const int tid = threadIdx.x;
    const int tx = tid & 15;
    const int ty = tid >> 4;
    const int bm = blockIdx.y * GBM;
    const int bn = blockIdx.x * GBN;

    // Load mapping: each thread loads one float4 from A and one from W per K-step
    const int lrow = tid >> 1;          // 0..127
    const int lcol = (tid & 1) << 2;    // 0 or 4
    const float* Ag = A + (size_t)(bm + lrow) * K + lcol;
    const float* Wg = W + (size_t)(bn + lrow) * K + lcol;

    float acc[8][8];
#pragma unroll
    for (int i = 0; i < 8; i++)
#pragma unroll
        for (int j = 0; j < 8; j++) acc[i][j] = 0.f;

    for (int k0 = 0; k0 < K; k0 += GBK) {
        float4 a4 = *(const float4*)(Ag + k0);
        float4 b4 = *(const float4*)(Wg + k0);
        __syncthreads();
        As[lcol + 0][lrow] = a4.x;
        As[lcol + 1][lrow] = a4.y;
        As[lcol + 2][lrow] = a4.z;
        As[lcol + 3][lrow] = a4.w;
        Bs[lcol + 0][lrow] = b4.x;
        Bs[lcol + 1][lrow] = b4.y;
        Bs[lcol + 2][lrow] = b4.z;
        Bs[lcol + 3][lrow] = b4.w;
        __syncthreads();

#pragma unroll
        for (int kk = 0; kk < GBK; kk++) {
            float ra[8], rb[8];
            *(float4*)&ra[0] = *(const float4*)&As[kk][ty * 8];
            *(float4*)&ra[4] = *(const float4*)&As[kk][ty * 8 + 4];
            *(float4*)&rb[0] = *(const float4*)&Bs[kk][tx * 8];
            *(float4*)&rb[4] = *(const float4*)&Bs[kk][tx * 8 + 4];
#pragma unroll
            for (int i = 0; i < 8; i++)
#pragma unroll
                for (int j = 0; j < 8; j++)
                    acc[i][j] += ra[i] * rb[j];
        }
    }

    float bi[8];
#pragma unroll
    for (int j = 0; j < 8; j++) bi[j] = bias[bn + tx * 8 + j];

#pragma unroll
    for (int i = 0; i < 8; i++) {
        float* Cp = C + (size_t)(bm + ty * 8 + i) * N + bn + tx * 8;
        float4 o0, o1;
        o0.x = acc[i][0] + bi[0];
        o0.y = acc[i][1] + bi[1];
        o0.z = acc[i][2] + bi[2];
        o0.w = acc[i][3] + bi[3];
        o1.x = acc[i][4] + bi[4];
        o1.y = acc[i][5] + bi[5];
        o1.z = acc[i][6] + bi[6];
        o1.w = acc[i][7] + bi[7];
        *(float4*)(Cp)     = o0;
        *(float4*)(Cp + 4) = o1;
    }
}

// ---------------------------------------------------------------------------
// Flash attention, causal. Q/K/V in (b, t, h, d) layout = (8192, 1024).
// Block = (q_tile of 64, one (b,h)). 256 threads as 16x16; each thread owns a
// 4x4 score tile and a 4(queries) x 4(dims) output accumulator.
// Online softmax; only lower-triangular k-tiles are visited.
// ---------------------------------------------------------------------------
#define AQ   64
#define AK   64
#define APAD 68    // row stride (floats): keeps float4 alignment, spreads banks

__global__ __launch_bounds__(256, 2)
void attn_kernel(const float* __restrict__ Qg, const float* __restrict__ Kg,
                 const float* __restrict__ Vg, float* __restrict__ Og)
{
    extern __shared__ float sm[];
    float* Qs  = sm;                 // [64 q rows][APAD]  (row-major, dims)
    float* Kst = sm + 64 * APAD;     // [64 dims][APAD]    (transposed: dim-major)
    float* Vs  = sm + 2 * 64 * APAD; // [64 keys][APAD]    (dims)
    float* Ps  = sm + 3 * 64 * APAD; // [64 q rows][APAD]  (probs over keys)

    const int tid = threadIdx.x;
    const int tx = tid & 15;
    const int ty = tid >> 4;
    const int qt = blockIdx.x;        // 0..31
    const int bh = blockIdx.y;        // 0..63
    const int b = bh >> 4;
    const int h = bh & 15;
    const float scale = 0.125f;       // 1/sqrt(64)

    const size_t base = ((size_t)b * SEQ) * D_MODEL + (size_t)h * DK;
    const int q0 = qt * AQ;
    const int ro = ty << 2;           // this thread's query-row offset (0..60)
    const int co = tx << 2;           // this thread's column offset (0..60)

    // Load Q tile (64 rows x 64 dims), float4 per thread iteration
    for (int idx = tid; idx < 64 * 16; idx += 256) {
        int r = idx >> 4;
        int c = (idx & 15) << 2;
        float4 v = *(const float4*)(Qg + base + (size_t)(q0 + r) * D_MODEL + c);
        *(float4*)&Qs[r * APAD + c] = v;
    }

    float m_i[4], l_i[4], o[4][4];
#pragma unroll
    for (int i = 0; i < 4; i++) {
        m_i[i] = -1e30f;
        l_i[i] = 0.f;
#pragma unroll
        for (int j = 0; j < 4; j++) o[i][j] = 0.f;
    }

    const int nkt = qt + 1;           // causal: only tiles at/below diagonal
    for (int kt = 0; kt < nkt; kt++) {
        __syncthreads();              // prior PV readers done; also covers Qs load
        const int k0 = kt * AK;
        // Load K (transposed into dim-major) and V tiles
        for (int idx = tid; idx < 64 * 16; idx += 256) {
            int r = idx >> 4;
            int c = (idx & 15) << 2;
            float4 kv = *(const float4*)(Kg + base + (size_t)(k0 + r) * D_MODEL + c);
            Kst[(c + 0) * APAD + r] = kv.x;
            Kst[(c + 1) * APAD + r] = kv.y;
            Kst[(c + 2) * APAD + r] = kv.z;
            Kst[(c + 3) * APAD + r] = kv.w;
            float4 vv = *(const float4*)(Vg + base + (size_t)(k0 + r) * D_MODEL + c);
            *(float4*)&Vs[r * APAD + c] = vv;
        }
        __syncthreads();

        // S = Q K^T (4x4 per thread)
        float s[4][4];
#pragma unroll
        for (int i = 0; i < 4; i++)
#pragma unroll
            for (int j = 0; j < 4; j++) s[i][j] = 0.f;

#pragma unroll 8
        for (int k = 0; k < 64; k++) {
            float a0 = Qs[(ro + 0) * APAD + k];
            float a1 = Qs[(ro + 1) * APAD + k];
            float a2 = Qs[(ro + 2) * APAD + k];
            float a3 = Qs[(ro + 3) * APAD + k];
            float4 bb = *(const float4*)&Kst[k * APAD + co];
            s[0][0] += a0 * bb.x; s[0][1] += a0 * bb.y; s[0][2] += a0 * bb.z; s[0][3] += a0 * bb.w;
            s[1][0] += a1 * bb.x; s[1][1] += a1 * bb.y; s[1][2] += a1 * bb.z; s[1][3] += a1 * bb.w;
            s[2][0] += a2 * bb.x; s[2][1] += a2 * bb.y; s[2][2] += a2 * bb.z; s[2][3] += a2 * bb.w;
            s[3][0] += a3 * bb.x; s[3][1] += a3 * bb.y; s[3][2] += a3 * bb.z; s[3][3] += a3 * bb.w;
        }

        // scale + causal mask
#pragma unroll
        for (int i = 0; i < 4; i++)
#pragma unroll
            for (int j = 0; j < 4; j++) {
                s[i][j] *= scale;
                if (k0 + co + j > q0 + ro + i) s[i][j] = -1e30f;
            }

        // Online softmax per query row; row spans the 16 tx-threads (same warp,
        // xor<=8 stays inside the 16-lane group)
#pragma unroll
        for (int i = 0; i < 4; i++) {
            float mx = fmaxf(fmaxf(s[i][0], s[i][1]), fmaxf(s[i][2], s[i][3]));
#pragma unroll
            for (int off = 8; off >= 1; off >>= 1)
                mx = fmaxf(mx, __shfl_xor_sync(0xffffffffu, mx, off));
            float mn = fmaxf(m_i[i], mx);
            float alpha = __expf(m_i[i] - mn);
            float p0 = __expf(s[i][0] - mn);
            float p1 = __expf(s[i][1] - mn);
            float p2 = __expf(s[i][2] - mn);
            float p3 = __expf(s[i][3] - mn);
            *(float4*)&Ps[(ro + i) * APAD + co] = make_float4(p0, p1, p2, p3);
            float rs = p0 + p1 + p2 + p3;
#pragma unroll
            for (int off = 8; off >= 1; off >>= 1)
                rs += __shfl_xor_sync(0xffffffffu, rs, off);
            l_i[i] = l_i[i] * alpha + rs;
            m_i[i] = mn;
            o[i][0] *= alpha; o[i][1] *= alpha; o[i][2] *= alpha; o[i][3] *= alpha;
        }
        __syncthreads();

        // O += P * V
#pragma unroll 8
        for (int kk = 0; kk < 64; kk++) {
            float4 vv = *(const float4*)&Vs[kk * APAD + co];
            float p0 = Ps[(ro + 0) * APAD + kk];
            float p1 = Ps[(ro + 1) * APAD + kk];
            float p2 = Ps[(ro + 2) * APAD + kk];
            float p3 = Ps[(ro + 3) * APAD + kk];
            o[0][0] += p0 * vv.x; o[0][1] += p0 * vv.y; o[0][2] += p0 * vv.z; o[0][3] += p0 * vv.w;
            o[1][0] += p1 * vv.x; o[1][1] += p1 * vv.y; o[1][2] += p1 * vv.z; o[1][3] += p1 * vv.w;
            o[2][0] += p2 * vv.x; o[2][1] += p2 * vv.y; o[2][2] += p2 * vv.z; o[2][3] += p2 * vv.w;
            o[3][0] += p3 * vv.x; o[3][1] += p3 * vv.y; o[3][2] += p3 * vv.z; o[3][3] += p3 * vv.w;
        }
    }

    // Normalize + write out (same (b,t,h,d) layout)
#pragma unroll
    for (int i = 0; i < 4; i++) {
        float inv = 1.f / l_i[i];
        float4 r;
        r.x = o[i][0] * inv;
        r.y = o[i][1] * inv;
        r.z = o[i][2] * inv;
        r.w = o[i][3] * inv;
        *(float4*)(Og + base + (size_t)(q0 + ro + i) * D_MODEL + co) = r;
    }
}

// ---------------------------------------------------------------------------
// Launch
// ---------------------------------------------------------------------------
extern "C" void kernel_launch(void* const* d_in, const int* in_sizes, int n_in,
                              void* d_out, int out_size)
{
    const float* x  = (const float*)d_in[0];
    // d_in[1] = mask (bool) — causal, implemented analytically
    const float* Wq = (const float*)d_in[2];
    const float* bq = (const float*)d_in[3];
    const float* Wk = (const float*)d_in[4];
    const float* bk = (const float*)d_in[5];
    const float* Wv = (const float*)d_in[6];
    const float* bv = (const float*)d_in[7];
    const float* Wo = (const float*)d_in[8];
    const float* bo = (const float*)d_in[9];
    float* out = (float*)d_out;

    float *gq, *gk, *gv, *ga;
    cudaGetSymbolAddress((void**)&gq, g_q);
    cudaGetSymbolAddress((void**)&gk, g_k);
    cudaGetSymbolAddress((void**)&gv, g_v);
    cudaGetSymbolAddress((void**)&ga, g_att);

    dim3 gg(D_MODEL / GBN, MROWS / GBM);   // (8, 64)
    gemm_nt_bias<<<gg, 256>>>(x, Wq, bq, gq, MROWS, D_MODEL, D_MODEL);
    gemm_nt_bias<<<gg, 256>>>(x, Wk, bk, gk, MROWS, D_MODEL, D_MODEL);
    gemm_nt_bias<<<gg, 256>>>(x, Wv, bv, gv, MROWS, D_MODEL, D_MODEL);

    const int smem = 4 * 64 * APAD * (int)sizeof(float);   // 69632 B
    cudaFuncSetAttribute(attn_kernel,
                         cudaFuncAttributeMaxDynamicSharedMemorySize, smem);
    attn_kernel<<<dim3(SEQ / AQ, BATCH * NHEADS), 256, smem>>>(gq, gk, gv, ga);

    gemm_nt_bias<<<gg, 256>>>(ga, Wo, bo, out, MROWS, D_MODEL, D_MODEL);
}

// round 3
// speedup vs baseline: 1.6161x; 1.6161x over previous
#include <cuda_runtime.h>
#include <cstdint>

#define D_MODEL 1024
#define NHEADS  16
#define DK      64
#define BATCH   4
#define SEQ     2048
#define MROWS   (BATCH*SEQ)   // 8192

// Scratch buffers (allocation-free rule: __device__ globals)
__device__ float g_q[MROWS * D_MODEL];
__device__ float g_k[MROWS * D_MODEL];
__device__ float g_v[MROWS * D_MODEL];
__device__ float g_att[MROWS * D_MODEL];

__device__ __forceinline__ uint32_t f2tf32(float f) {
    uint32_t u;
    asm("cvt.rna.tf32.f32 %0, %1;" : "=r"(u) : "f"(f));
    return u;
}

// D += A(16x8, row) * B(8x8, col: B[n][k] k-contig)  -- tf32, fp32 accum
__device__ __forceinline__ void mma1688(float* d, const uint32_t* a, const uint32_t* b) {
    asm volatile(
        "mma.sync.aligned.m16n8k8.row.col.f32.tf32.tf32.f32 "
        "{%0,%1,%2,%3}, {%4,%5,%6,%7}, {%8,%9}, {%0,%1,%2,%3};"
        : "+f"(d[0]), "+f"(d[1]), "+f"(d[2]), "+f"(d[3])
        : "r"(a[0]), "r"(a[1]), "r"(a[2]), "r"(a[3]), "r"(b[0]), "r"(b[1]));
}

// ===========================================================================
// Tensor-core GEMM: C[m,n] = sum_k A[m,k]*W[n,k] + bias[n]
// Block 128x128, BK=16, 256 threads. Warp tile 64x32 (wm=wid&1, wn=wid>>1).
// A smem [128][k:16] stride 20 (conflict-free frag LDS);
// B smem [k:16][128] stride 136 (conflict-free frag LDS).
// ===========================================================================
#define ASTR 20
#define BSTR 136

__global__ __launch_bounds__(256, 2)
void gemm_mma(const float* __restrict__ A, const float* __restrict__ W,
              const float* __restrict__ bias, float* __restrict__ C,
              int M, int N, int K)
{
    __shared__ uint32_t As[2][128 * ASTR];
    __shared__ uint32_t Bs[2][16 * BSTR];

    const int tid = threadIdx.x;
    const int lane = tid & 31;
    const int wid = tid >> 5;
    const int wm = wid & 1;         // 0..1 (64 rows each)
    const int wn = wid >> 1;        // 0..3 (32 cols each)
    const int bm = blockIdx.y * 128;
    const int bn = blockIdx.x * 128;
    const int g = lane >> 2;        // group 0..7
    const int t = lane & 3;         // thread-in-group 0..3

    float4 ra[2], rb[2];

    auto ldg = [&](int kt) {
        const float* Ag = A + (size_t)bm * K + kt * 16;
        const float* Wg = W + (size_t)bn * K + kt * 16;
#pragma unroll
        for (int i = 0; i < 2; i++) {
            int f = tid + i * 256;          // float4 id 0..511
            int row = f >> 2;
            int k0 = (f & 3) << 2;
            ra[i] = *(const float4*)(Ag + (size_t)row * K + k0);
            rb[i] = *(const float4*)(Wg + (size_t)row * K + k0);
        }
    };
    auto sts = [&](int buf) {
#pragma unroll
        for (int i = 0; i < 2; i++) {
            int f = tid + i * 256;
            int row = f >> 2;
            int k0 = (f & 3) << 2;
            uint4 ta = make_uint4(f2tf32(ra[i].x), f2tf32(ra[i].y),
                                  f2tf32(ra[i].z), f2tf32(ra[i].w));
            *(uint4*)&As[buf][row * ASTR + k0] = ta;
            Bs[buf][(k0 + 0) * BSTR + row] = f2tf32(rb[i].x);
            Bs[buf][(k0 + 1) * BSTR + row] = f2tf32(rb[i].y);
            Bs[buf][(k0 + 2) * BSTR + row] = f2tf32(rb[i].z);
            Bs[buf][(k0 + 3) * BSTR + row] = f2tf32(rb[i].w);
        }
    };

    float acc[4][4][4];
#pragma unroll
    for (int fm = 0; fm < 4; fm++)
#pragma unroll
        for (int fn = 0; fn < 4; fn++)
#pragma unroll
            for (int j = 0; j < 4; j++) acc[fm][fn][j] = 0.f;

    ldg(0);
    sts(0);
    __syncthreads();

    const int NKT = K / 16;   // 64
    for (int kt = 0; kt < NKT; kt++) {
        const int buf = kt & 1;
        if (kt + 1 < NKT) ldg(kt + 1);

#pragma unroll
        for (int kk = 0; kk < 2; kk++) {
            const int k8 = kk * 8;
            uint32_t a[4][4], b[4][2];
#pragma unroll
            for (int fm = 0; fm < 4; fm++) {
                const int r0 = wm * 64 + fm * 16 + g;
                const int c0 = k8 + t;
                a[fm][0] = As[buf][r0 * ASTR + c0];
                a[fm][1] = As[buf][(r0 + 8) * ASTR + c0];
                a[fm][2] = As[buf][r0 * ASTR + c0 + 4];
                a[fm][3] = As[buf][(r0 + 8) * ASTR + c0 + 4];
            }
#pragma unroll
            for (int fn = 0; fn < 4; fn++) {
                const int cn = wn * 32 + fn * 8 + g;
                const int rk = k8 + t;
                b[fn][0] = Bs[buf][rk * BSTR + cn];
                b[fn][1] = Bs[buf][(rk + 4) * BSTR + cn];
            }
#pragma unroll
            for (int fm = 0; fm < 4; fm++)
#pragma unroll
                for (int fn = 0; fn < 4; fn++)
                    mma1688(acc[fm][fn], a[fm], b[fn]);
        }

        if (kt + 1 < NKT) sts((kt + 1) & 1);
        __syncthreads();
    }

    // Epilogue: accum + bias -> GMEM (float2 per half-frag)
#pragma unroll
    for (int fm = 0; fm < 4; fm++) {
        const int row = bm + wm * 64 + fm * 16 + g;
#pragma unroll
        for (int fn = 0; fn < 4; fn++) {
            const int col = bn + wn * 32 + fn * 8 + 2 * t;
            const float b0 = bias[col];
            const float b1 = bias[col + 1];
            float2 v0 = make_float2(acc[fm][fn][0] + b0, acc[fm][fn][1] + b1);
            float2 v1 = make_float2(acc[fm][fn][2] + b0, acc[fm][fn][3] + b1);
            *(float2*)(C + (size_t)row * N + col) = v0;
            *(float2*)(C + (size_t)(row + 8) * N + col) = v1;
        }
    }
}

// ---------------------------------------------------------------------------
// Flash attention, causal (SIMT fp32; tensor-core conversion next round).
// ---------------------------------------------------------------------------
#define AQ   64
#define AK   64
#define APAD 68

__global__ __launch_bounds__(256, 2)
void attn_kernel(const float* __restrict__ Qg, const float* __restrict__ Kg,
                 const float* __restrict__ Vg, float* __restrict__ Og)
{
    extern __shared__ float smf[];
    float* Qs  = smf;
    float* Kst = smf + 64 * APAD;
    float* Vs  = smf + 2 * 64 * APAD;
    float* Ps  = smf + 3 * 64 * APAD;

    const int tid = threadIdx.x;
    const int tx = tid & 15;
    const int ty = tid >> 4;
    const int qt = blockIdx.x;
    const int bh = blockIdx.y;
    const int b = bh >> 4;
    const int h = bh & 15;
    const float scale = 0.125f;

    const size_t base = ((size_t)b * SEQ) * D_MODEL + (size_t)h * DK;
    const int q0 = qt * AQ;
    const int ro = ty << 2;
    const int co = tx << 2;

    for (int idx = tid; idx < 64 * 16; idx += 256) {
        int r = idx >> 4;
        int c = (idx & 15) << 2;
        float4 v = *(const float4*)(Qg + base + (size_t)(q0 + r) * D_MODEL + c);
        *(float4*)&Qs[r * APAD + c] = v;
    }

    float m_i[4], l_i[4], o[4][4];
#pragma unroll
    for (int i = 0; i < 4; i++) {
        m_i[i] = -1e30f;
        l_i[i] = 0.f;
#pragma unroll
        for (int j = 0; j < 4; j++) o[i][j] = 0.f;
    }

    const int nkt = qt + 1;
    for (int kt = 0; kt < nkt; kt++) {
        __syncthreads();
        const int k0 = kt * AK;
        for (int idx = tid; idx < 64 * 16; idx += 256) {
            int r = idx >> 4;
            int c = (idx & 15) << 2;
            float4 kv = *(const float4*)(Kg + base + (size_t)(k0 + r) * D_MODEL + c);
            Kst[(c + 0) * APAD + r] = kv.x;
            Kst[(c + 1) * APAD + r] = kv.y;
            Kst[(c + 2) * APAD + r] = kv.z;
            Kst[(c + 3) * APAD + r] = kv.w;
            float4 vv = *(const float4*)(Vg + base + (size_t)(k0 + r) * D_MODEL + c);
            *(float4*)&Vs[r * APAD + c] = vv;
        }
        __syncthreads();

        float s[4][4];
#pragma unroll
        for (int i = 0; i < 4; i++)
#pragma unroll
            for (int j = 0; j < 4; j++) s[i][j] = 0.f;

#pragma unroll 8
        for (int k = 0; k < 64; k++) {
            float a0 = Qs[(ro + 0) * APAD + k];
            float a1 = Qs[(ro + 1) * APAD + k];
            float a2 = Qs[(ro + 2) * APAD + k];
            float a3 = Qs[(ro + 3) * APAD + k];
            float4 bb = *(const float4*)&Kst[k * APAD + co];
            s[0][0] += a0 * bb.x; s[0][1] += a0 * bb.y; s[0][2] += a0 * bb.z; s[0][3] += a0 * bb.w;
            s[1][0] += a1 * bb.x; s[1][1] += a1 * bb.y; s[1][2] += a1 * bb.z; s[1][3] += a1 * bb.w;
            s[2][0] += a2 * bb.x; s[2][1] += a2 * bb.y; s[2][2] += a2 * bb.z; s[2][3] += a2 * bb.w;
            s[3][0] += a3 * bb.x; s[3][1] += a3 * bb.y; s[3][2] += a3 * bb.z; s[3][3] += a3 * bb.w;
        }

#pragma unroll
        for (int i = 0; i < 4; i++)
#pragma unroll
            for (int j = 0; j < 4; j++) {
                s[i][j] *= scale;
                if (k0 + co + j > q0 + ro + i) s[i][j] = -1e30f;
            }

#pragma unroll
        for (int i = 0; i < 4; i++) {
            float mx = fmaxf(fmaxf(s[i][0], s[i][1]), fmaxf(s[i][2], s[i][3]));
#pragma unroll
            for (int off = 8; off >= 1; off >>= 1)
                mx = fmaxf(mx, __shfl_xor_sync(0xffffffffu, mx, off));
            float mn = fmaxf(m_i[i], mx);
            float alpha = __expf(m_i[i] - mn);
            float p0 = __expf(s[i][0] - mn);
            float p1 = __expf(s[i][1] - mn);
            float p2 = __expf(s[i][2] - mn);
            float p3 = __expf(s[i][3] - mn);
            *(float4*)&Ps[(ro + i) * APAD + co] = make_float4(p0, p1, p2, p3);
            float rs = p0 + p1 + p2 + p3;
#pragma unroll
            for (int off = 8; off >= 1; off >>= 1)
                rs += __shfl_xor_sync(0xffffffffu, rs, off);
            l_i[i] = l_i[i] * alpha + rs;
            m_i[i] = mn;
            o[i][0] *= alpha; o[i][1] *= alpha; o[i][2] *= alpha; o[i][3] *= alpha;
        }
        __syncthreads();

#pragma unroll 8
        for (int kk = 0; kk < 64; kk++) {
            float4 vv = *(const float4*)&Vs[kk * APAD + co];
            float p0 = Ps[(ro + 0) * APAD + kk];
            float p1 = Ps[(ro + 1) * APAD + kk];
            float p2 = Ps[(ro + 2) * APAD + kk];
            float p3 = Ps[(ro + 3) * APAD + kk];
            o[0][0] += p0 * vv.x; o[0][1] += p0 * vv.y; o[0][2] += p0 * vv.z; o[0][3] += p0 * vv.w;
            o[1][0] += p1 * vv.x; o[1][1] += p1 * vv.y; o[1][2] += p1 * vv.z; o[1][3] += p1 * vv.w;
            o[2][0] += p2 * vv.x; o[2][1] += p2 * vv.y; o[2][2] += p2 * vv.z; o[2][3] += p2 * vv.w;
            o[3][0] += p3 * vv.x; o[3][1] += p3 * vv.y; o[3][2] += p3 * vv.z; o[3][3] += p3 * vv.w;
        }
    }

#pragma unroll
    for (int i = 0; i < 4; i++) {
        float inv = 1.f / l_i[i];
        float4 r;
        r.x = o[i][0] * inv;
        r.y = o[i][1] * inv;
        r.z = o[i][2] * inv;
        r.w = o[i][3] * inv;
        *(float4*)(Og + base + (size_t)(q0 + ro + i) * D_MODEL + co) = r;
    }
}

// ---------------------------------------------------------------------------
// Launch
// ---------------------------------------------------------------------------
extern "C" void kernel_launch(void* const* d_in, const int* in_sizes, int n_in,
                              void* d_out, int out_size)
{
    const float* x  = (const float*)d_in[0];
    // d_in[1] = mask (bool) — causal, implemented analytically
    const float* Wq = (const float*)d_in[2];
    const float* bq = (const float*)d_in[3];
    const float* Wk = (const float*)d_in[4];
    const float* bk = (const float*)d_in[5];
    const float* Wv = (const float*)d_in[6];
    const float* bv = (const float*)d_in[7];
    const float* Wo = (const float*)d_in[8];
    const float* bo = (const float*)d_in[9];
    float* out = (float*)d_out;

    float *gq, *gk, *gv, *ga;
    cudaGetSymbolAddress((void**)&gq, g_q);
    cudaGetSymbolAddress((void**)&gk, g_k);
    cudaGetSymbolAddress((void**)&gv, g_v);
    cudaGetSymbolAddress((void**)&ga, g_att);

    dim3 gg(D_MODEL / 128, MROWS / 128);   // (8, 64)
    gemm_mma<<<gg, 256>>>(x, Wq, bq, gq, MROWS, D_MODEL, D_MODEL);
    gemm_mma<<<gg, 256>>>(x, Wk, bk, gk, MROWS, D_MODEL, D_MODEL);
    gemm_mma<<<gg, 256>>>(x, Wv, bv, gv, MROWS, D_MODEL, D_MODEL);

    const int asmem = 4 * 64 * APAD * (int)sizeof(float);   // 69632 B
    cudaFuncSetAttribute(attn_kernel,
                         cudaFuncAttributeMaxDynamicSharedMemorySize, asmem);
    attn_kernel<<<dim3(SEQ / AQ, BATCH * NHEADS), 256, asmem>>>(gq, gk, gv, ga);

    gemm_mma<<<gg, 256>>>(ga, Wo, bo, out, MROWS, D_MODEL, D_MODEL);
}

// round 5
// speedup vs baseline: 2.9499x; 1.8253x over previous
#include <cuda_runtime.h>
#include <cstdint>

#define D_MODEL 1024
#define NHEADS  16
#define DK      64
#define BATCH   4
#define SEQ     2048
#define MROWS   (BATCH*SEQ)   // 8192

// Scratch buffers (allocation-free rule: __device__ globals)
__device__ float g_q[MROWS * D_MODEL];
__device__ float g_k[MROWS * D_MODEL];
__device__ float g_v[MROWS * D_MODEL];
__device__ float g_att[MROWS * D_MODEL];

__device__ __forceinline__ uint32_t f2tf32(float f) {
    uint32_t u;
    asm("cvt.rna.tf32.f32 %0, %1;" : "=r"(u) : "f"(f));
    return u;
}

// D += A(16x8, row) * B(8x8, col)  -- tf32, fp32 accum
__device__ __forceinline__ void mma1688(float* d, const uint32_t* a, uint32_t b0, uint32_t b1) {
    asm volatile(
        "mma.sync.aligned.m16n8k8.row.col.f32.tf32.tf32.f32 "
        "{%0,%1,%2,%3}, {%4,%5,%6,%7}, {%8,%9}, {%0,%1,%2,%3};"
        : "+f"(d[0]), "+f"(d[1]), "+f"(d[2]), "+f"(d[3])
        : "r"(a[0]), "r"(a[1]), "r"(a[2]), "r"(a[3]), "r"(b0), "r"(b1));
}

// ===========================================================================
// Tensor-core GEMM: C[m,n] = sum_k A[m,k]*W[n,k] + bias[n]
// Block 128x128, BK=16, 256 threads. Warp tile 64x32.
// ===========================================================================
#define ASTR 20
#define BSTR 136

__global__ __launch_bounds__(256, 2)
void gemm_mma(const float* __restrict__ A, const float* __restrict__ W,
              const float* __restrict__ bias, float* __restrict__ C,
              int M, int N, int K)
{
    __shared__ uint32_t As[2][128 * ASTR];
    __shared__ uint32_t Bs[2][16 * BSTR];

    const int tid = threadIdx.x;
    const int lane = tid & 31;
    const int wid = tid >> 5;
    const int wm = wid & 1;
    const int wn = wid >> 1;
    const int bm = blockIdx.y * 128;
    const int bn = blockIdx.x * 128;
    const int g = lane >> 2;
    const int t = lane & 3;

    float4 ra[2], rb[2];

    auto ldg = [&](int kt) {
        const float* Ag = A + (size_t)bm * K + kt * 16;
        const float* Wg = W + (size_t)bn * K + kt * 16;
#pragma unroll
        for (int i = 0; i < 2; i++) {
            int f = tid + i * 256;
            int row = f >> 2;
            int k0 = (f & 3) << 2;
            ra[i] = *(const float4*)(Ag + (size_t)row * K + k0);
            rb[i] = *(const float4*)(Wg + (size_t)row * K + k0);
        }
    };
    auto sts = [&](int buf) {
#pragma unroll
        for (int i = 0; i < 2; i++) {
            int f = tid + i * 256;
            int row = f >> 2;
            int k0 = (f & 3) << 2;
            uint4 ta = make_uint4(f2tf32(ra[i].x), f2tf32(ra[i].y),
                                  f2tf32(ra[i].z), f2tf32(ra[i].w));
            *(uint4*)&As[buf][row * ASTR + k0] = ta;
            Bs[buf][(k0 + 0) * BSTR + row] = f2tf32(rb[i].x);
            Bs[buf][(k0 + 1) * BSTR + row] = f2tf32(rb[i].y);
            Bs[buf][(k0 + 2) * BSTR + row] = f2tf32(rb[i].z);
            Bs[buf][(k0 + 3) * BSTR + row] = f2tf32(rb[i].w);
        }
    };

    float acc[4][4][4];
#pragma unroll
    for (int fm = 0; fm < 4; fm++)
#pragma unroll
        for (int fn = 0; fn < 4; fn++)
#pragma unroll
            for (int j = 0; j < 4; j++) acc[fm][fn][j] = 0.f;

    ldg(0);
    sts(0);
    __syncthreads();

    const int NKT = K / 16;
    for (int kt = 0; kt < NKT; kt++) {
        const int buf = kt & 1;
        if (kt + 1 < NKT) ldg(kt + 1);

#pragma unroll
        for (int kk = 0; kk < 2; kk++) {
            const int k8 = kk * 8;
            uint32_t a[4][4], b[4][2];
#pragma unroll
            for (int fm = 0; fm < 4; fm++) {
                const int r0 = wm * 64 + fm * 16 + g;
                const int c0 = k8 + t;
                a[fm][0] = As[buf][r0 * ASTR + c0];
                a[fm][1] = As[buf][(r0 + 8) * ASTR + c0];
                a[fm][2] = As[buf][r0 * ASTR + c0 + 4];
                a[fm][3] = As[buf][(r0 + 8) * ASTR + c0 + 4];
            }
#pragma unroll
            for (int fn = 0; fn < 4; fn++) {
                const int cn = wn * 32 + fn * 8 + g;
                const int rk = k8 + t;
                b[fn][0] = Bs[buf][rk * BSTR + cn];
                b[fn][1] = Bs[buf][(rk + 4) * BSTR + cn];
            }
#pragma unroll
            for (int fm = 0; fm < 4; fm++)
#pragma unroll
                for (int fn = 0; fn < 4; fn++)
                    mma1688(acc[fm][fn], a[fm], b[fn][0], b[fn][1]);
        }

        if (kt + 1 < NKT) sts((kt + 1) & 1);
        __syncthreads();
    }

#pragma unroll
    for (int fm = 0; fm < 4; fm++) {
        const int row = bm + wm * 64 + fm * 16 + g;
#pragma unroll
        for (int fn = 0; fn < 4; fn++) {
            const int col = bn + wn * 32 + fn * 8 + 2 * t;
            const float b0 = bias[col];
            const float b1 = bias[col + 1];
            float2 v0 = make_float2(acc[fm][fn][0] + b0, acc[fm][fn][1] + b1);
            float2 v1 = make_float2(acc[fm][fn][2] + b0, acc[fm][fn][3] + b1);
            *(float2*)(C + (size_t)row * N + col) = v0;
            *(float2*)(C + (size_t)(row + 8) * N + col) = v1;
        }
    }
}

// ===========================================================================
// Flash attention, causal, tf32 mma.sync.
// Block = 64 q-rows x one (b,h). 4 warps, warp owns 16 q-rows.
// K,P,Q smem stride 68 (bank 4g+t bijection); V smem stride 72 (8t+g).
// ===========================================================================
#define KP_STR 68
#define V_STR  72

__global__ __launch_bounds__(128, 4)
void attn_mma(const float* __restrict__ Qg, const float* __restrict__ Kg,
              const float* __restrict__ Vg, float* __restrict__ Og)
{
    extern __shared__ uint32_t smu[];
    uint32_t* Ks = smu;                    // [64][KP_STR]
    uint32_t* Vs = smu + 64 * KP_STR;      // [64][V_STR]
    uint32_t* Ps = Vs + 64 * V_STR;        // [64][KP_STR]  (also Q staging)

    const int tid = threadIdx.x;
    const int lane = tid & 31;
    const int wid = tid >> 5;
    const int g = lane >> 2;
    const int t = lane & 3;
    const int qt = (int)gridDim.x - 1 - (int)blockIdx.x;   // heavy tiles first
    const int bh = blockIdx.y;
    const int b = bh >> 4;
    const int h = bh & 15;

    const size_t base = ((size_t)b * SEQ) * D_MODEL + (size_t)h * DK;
    const int q0 = qt * 64;
    const int r0 = wid * 16;

    // ---- stage Q tile into Ps, then cache A-frags in registers ----
    for (int idx = tid; idx < 64 * 16; idx += 128) {
        int r = idx >> 4;
        int c = (idx & 15) << 2;
        float4 v = *(const float4*)(Qg + base + (size_t)(q0 + r) * D_MODEL + c);
        uint32_t* p = &Ps[r * KP_STR + c];
        p[0] = f2tf32(v.x); p[1] = f2tf32(v.y); p[2] = f2tf32(v.z); p[3] = f2tf32(v.w);
    }
    __syncthreads();
    uint32_t qf[8][4];
#pragma unroll
    for (int fk = 0; fk < 8; fk++) {
        qf[fk][0] = Ps[(r0 + g) * KP_STR + fk * 8 + t];
        qf[fk][1] = Ps[(r0 + g + 8) * KP_STR + fk * 8 + t];
        qf[fk][2] = Ps[(r0 + g) * KP_STR + fk * 8 + t + 4];
        qf[fk][3] = Ps[(r0 + g + 8) * KP_STR + fk * 8 + t + 4];
    }

    float m_i[2] = {-1e30f, -1e30f};
    float l_i[2] = {0.f, 0.f};
    float o[8][4];
#pragma unroll
    for (int fn = 0; fn < 8; fn++)
#pragma unroll
        for (int j = 0; j < 4; j++) o[fn][j] = 0.f;

    const float sc = 0.125f;   // 1/sqrt(64)

    for (int kt = 0; kt <= qt; kt++) {
        __syncthreads();       // prior iter's Vs/Ks reads + Ps(Q) frag loads done
        const int k0g = kt * 64;
        for (int idx = tid; idx < 64 * 16; idx += 128) {
            int r = idx >> 4;
            int c = (idx & 15) << 2;
            float4 kv = *(const float4*)(Kg + base + (size_t)(k0g + r) * D_MODEL + c);
            uint32_t* kp = &Ks[r * KP_STR + c];
            kp[0] = f2tf32(kv.x); kp[1] = f2tf32(kv.y); kp[2] = f2tf32(kv.z); kp[3] = f2tf32(kv.w);
            float4 vv = *(const float4*)(Vg + base + (size_t)(k0g + r) * D_MODEL + c);
            uint32_t* vp = &Vs[r * V_STR + c];
            vp[0] = f2tf32(vv.x); vp[1] = f2tf32(vv.y); vp[2] = f2tf32(vv.z); vp[3] = f2tf32(vv.w);
        }
        __syncthreads();

        // ---- S = Q K^T : per-thread C-frags s[8][4] ----
        float s[8][4];
#pragma unroll
        for (int fn = 0; fn < 8; fn++)
#pragma unroll
            for (int j = 0; j < 4; j++) s[fn][j] = 0.f;

#pragma unroll
        for (int fn = 0; fn < 8; fn++) {
            const uint32_t* krow = &Ks[(fn * 8 + g) * KP_STR];
#pragma unroll
            for (int fk = 0; fk < 8; fk++) {
                uint32_t b0 = krow[fk * 8 + t];
                uint32_t b1 = krow[fk * 8 + t + 4];
                mma1688(s[fn], qf[fk], b0, b1);
            }
        }

        // ---- scale (+ diagonal mask) ----
        if (kt == qt) {
#pragma unroll
            for (int fn = 0; fn < 8; fn++) {
                int c0 = fn * 8 + 2 * t;       // local col; local row = r0+g(+8)
#pragma unroll
                for (int j = 0; j < 4; j++) {
                    int col = c0 + (j & 1);
                    int row = r0 + g + ((j >> 1) << 3);
                    s[fn][j] = (col > row) ? -1e30f : s[fn][j] * sc;
                }
            }
        } else {
#pragma unroll
            for (int fn = 0; fn < 8; fn++)
#pragma unroll
                for (int j = 0; j < 4; j++) s[fn][j] *= sc;
        }

        // ---- online softmax (per half: rows g and g+8) ----
#pragma unroll
        for (int h2 = 0; h2 < 2; h2++) {
            const int j0 = h2 * 2;
            float mx = -1e30f;
#pragma unroll
            for (int fn = 0; fn < 8; fn++)
                mx = fmaxf(mx, fmaxf(s[fn][j0], s[fn][j0 + 1]));
            mx = fmaxf(mx, __shfl_xor_sync(0xffffffffu, mx, 1));
            mx = fmaxf(mx, __shfl_xor_sync(0xffffffffu, mx, 2));
            float mn = fmaxf(m_i[h2], mx);
            float al = __expf(m_i[h2] - mn);
            float ls = 0.f;
#pragma unroll
            for (int fn = 0; fn < 8; fn++) {
                float p0 = __expf(s[fn][j0] - mn);
                float p1 = __expf(s[fn][j0 + 1] - mn);
                s[fn][j0] = p0;
                s[fn][j0 + 1] = p1;
                ls += p0 + p1;
            }
            ls += __shfl_xor_sync(0xffffffffu, ls, 1);
            ls += __shfl_xor_sync(0xffffffffu, ls, 2);
            l_i[h2] = l_i[h2] * al + ls;
            m_i[h2] = mn;
#pragma unroll
            for (int fn = 0; fn < 8; fn++) {
                o[fn][j0] *= al;
                o[fn][j0 + 1] *= al;
            }
        }

        // ---- P -> smem (warp-private rows), reload as A-frags ----
#pragma unroll
        for (int fn = 0; fn < 8; fn++) {
            uint32_t* p0 = &Ps[(r0 + g) * KP_STR + fn * 8 + 2 * t];
            p0[0] = f2tf32(s[fn][0]);
            p0[1] = f2tf32(s[fn][1]);
            uint32_t* p1 = &Ps[(r0 + g + 8) * KP_STR + fn * 8 + 2 * t];
            p1[0] = f2tf32(s[fn][2]);
            p1[1] = f2tf32(s[fn][3]);
        }
        __syncwarp();

        uint32_t pf[8][4];
#pragma unroll
        for (int fk = 0; fk < 8; fk++) {
            pf[fk][0] = Ps[(r0 + g) * KP_STR + fk * 8 + t];
            pf[fk][1] = Ps[(r0 + g + 8) * KP_STR + fk * 8 + t];
            pf[fk][2] = Ps[(r0 + g) * KP_STR + fk * 8 + t + 4];
            pf[fk][3] = Ps[(r0 + g + 8) * KP_STR + fk * 8 + t + 4];
        }

        // ---- O += P V ----
#pragma unroll
        for (int fn = 0; fn < 8; fn++) {
#pragma unroll
            for (int fk = 0; fk < 8; fk++) {
                uint32_t b0 = Vs[(fk * 8 + t) * V_STR + fn * 8 + g];
                uint32_t b1 = Vs[(fk * 8 + t + 4) * V_STR + fn * 8 + g];
                mma1688(o[fn], pf[fk], b0, b1);
            }
        }
    }

    // ---- epilogue ----
    const float inv0 = 1.f / l_i[0];
    const float inv1 = 1.f / l_i[1];
    const int row0 = q0 + r0 + g;
#pragma unroll
    for (int fn = 0; fn < 8; fn++) {
        const int col = fn * 8 + 2 * t;
        float2 v0 = make_float2(o[fn][0] * inv0, o[fn][1] * inv0);
        float2 v1 = make_float2(o[fn][2] * inv1, o[fn][3] * inv1);
        *(float2*)(Og + base + (size_t)row0 * D_MODEL + col) = v0;
        *(float2*)(Og + base + (size_t)(row0 + 8) * D_MODEL + col) = v1;
    }
}

// ---------------------------------------------------------------------------
// Launch
// ---------------------------------------------------------------------------
extern "C" void kernel_launch(void* const* d_in, const int* in_sizes, int n_in,
                              void* d_out, int out_size)
{
    const float* x  = (const float*)d_in[0];
    // d_in[1] = mask (bool) — causal, implemented analytically
    const float* Wq = (const float*)d_in[2];
    const float* bq = (const float*)d_in[3];
    const float* Wk = (const float*)d_in[4];
    const float* bk = (const float*)d_in[5];
    const float* Wv = (const float*)d_in[6];
    const float* bv = (const float*)d_in[7];
    const float* Wo = (const float*)d_in[8];
    const float* bo = (const float*)d_in[9];
    float* out = (float*)d_out;

    float *gq, *gk, *gv, *ga;
    cudaGetSymbolAddress((void**)&gq, g_q);
    cudaGetSymbolAddress((void**)&gk, g_k);
    cudaGetSymbolAddress((void**)&gv, g_v);
    cudaGetSymbolAddress((void**)&ga, g_att);

    dim3 gg(D_MODEL / 128, MROWS / 128);   // (8, 64)
    gemm_mma<<<gg, 256>>>(x, Wq, bq, gq, MROWS, D_MODEL, D_MODEL);
    gemm_mma<<<gg, 256>>>(x, Wk, bk, gk, MROWS, D_MODEL, D_MODEL);
    gemm_mma<<<gg, 256>>>(x, Wv, bv, gv, MROWS, D_MODEL, D_MODEL);

    const int asmem = (64 * KP_STR + 64 * V_STR + 64 * KP_STR) * (int)sizeof(uint32_t); // 53248
    cudaFuncSetAttribute(attn_mma,
                         cudaFuncAttributeMaxDynamicSharedMemorySize, asmem);
    attn_mma<<<dim3(SEQ / 64, BATCH * NHEADS), 128, asmem>>>(gq, gk, gv, ga);

    gemm_mma<<<gg, 256>>>(ga, Wo, bo, out, MROWS, D_MODEL, D_MODEL);
}